// round 7
// baseline (speedup 1.0000x reference)
#include <cuda_runtime.h>

#define CDIM  768
#define CDIM4 192           // CDIM/4
#define NTHREADS 256
#define NBLOCKS  304        // 152 SMs * 2 blocks
#define TM 128
#define TN 128
#define TK 32
#define KTILES (CDIM / TK)  // 24
#define JTILES (CDIM / TN)  // 6
#define QOFF 4096           // scratch stride (max B = 4096)
#define CHUNK4 2048         // float4 per copy chunk (32 KB)
#define TMP (TM + 4)        // padded smem row

// quadratic-form scratch: [0,B) text, [QOFF,QOFF+B) graph. MUST be zero at
// kernel entry: zero-initialized at load; re-zeroed by last-exiting block.
__device__ float g_quad[2 * QOFF];
__device__ float g_ubuf[QOFF * CDIM];   // blended user rows (finalize -> fixup)
__device__ unsigned g_ctr;        // work-queue head
__device__ unsigned g_passed;     // blocks that finished all pre-finalize work
__device__ unsigned g_exit;       // exited blocks

// user_index may be int64 (declared) or int32 (JAX x64-off default).
__device__ __forceinline__ int detect_is64(const void* uptr, int B, long long nrows) {
    if (B < 2) return 1;
    long long v = ((const long long*)uptr)[B / 2 - 1];
    return (v >= 0 && v < nrows) ? 1 : 0;
}
__device__ __forceinline__ long long load_idx(const void* uptr, int i, int is64) {
    if (is64) return ((const long long*)uptr)[i];
    return (long long)((const int*)uptr)[i];
}

// ---- packed fp32x2 helpers (SASS FFMA2; ptxas never auto-fuses) ----
__device__ __forceinline__ unsigned long long dup2(float a) {
    unsigned long long d; unsigned ai = __float_as_uint(a);
    asm("mov.b64 %0, {%1, %1};" : "=l"(d) : "r"(ai));
    return d;
}
__device__ __forceinline__ void fma2(unsigned long long& acc,
                                     unsigned long long a, unsigned long long b) {
    asm("fma.rn.f32x2 %0, %1, %2, %0;" : "+l"(acc) : "l"(a), "l"(b));
}
__device__ __forceinline__ float2 unpack2(unsigned long long v) {
    float2 r;
    asm("mov.b64 {%0, %1}, %2;" : "=f"(r.x), "=f"(r.y) : "l"(v));
    return r;
}

// ---------------------------------------------------------------------------
// Mega kernel (SM branch). Work items:
//   [0, NITEMS): mixed — i%P==0 && i/P<NG -> GEMM tile; else text copy chunk
//   [NITEMS, TOTAL): finalize text rows (wait g_passed == gridDim.x first).
// Each block signals g_passed ONCE (fence+atomic) when it first grabs an
// item >= NITEMS. The user tensor is copied concurrently by copy engines;
// mega never touches outU — blended user rows go to g_ubuf for fixup.
// ---------------------------------------------------------------------------
__global__ void __launch_bounds__(NTHREADS, 2)
mega(const float* __restrict__ text,
     const float* __restrict__ user,
     const void*  __restrict__ uidx,
     const float* __restrict__ Wt,
     const float* __restrict__ bt,
     const float* __restrict__ Wg,
     const float* __restrict__ bg,
     float* __restrict__ outAll,           // outT (text_n) then outU (user_n)
     int B, long long SC,
     long long text_n, long long user_rows,
     unsigned NG, unsigned P, unsigned NITEMS, unsigned TOTAL)
{
    __shared__ float As[TK][TMP];
    __shared__ float Bs[TK][TMP];
    __shared__ unsigned s_item;

    const int tid  = threadIdx.x;
    const int warp = tid >> 5;
    const int lane = tid & 31;
    const int tx   = tid & 15;    // j-fragment index
    const int ty   = tid >> 4;    // row-fragment index

    const float4* __restrict__ tin = (const float4*)text;
    float4* __restrict__ dall = (float4*)outAll;

    const unsigned perM = NG >> 1;

    if (tid == 0) s_item = atomicAdd(&g_ctr, 1u);
    __syncthreads();
    unsigned item = s_item;
    bool passed = false;

    const int is64 = detect_is64(uidx, B, user_rows);

    for (;;) {
        // once per block: signal that all its copy/GEMM stores are visible
        if (!passed && item >= NITEMS) {
            __threadfence();
            __syncthreads();
            if (tid == 0) atomicAdd(&g_passed, 1u);
            passed = true;
        }
        if (item >= TOTAL) break;

        unsigned g = item / P;
        bool isGemm = (item < NITEMS) && (item - g * P == 0u) && (g < NG);

        if (isGemm) {
            // ================= GEMM bilinear-form tile =================
            const int isG = (g >= perM) ? 1 : 0;
            const int qq  = isG ? (int)(g - perM) : (int)g;
            const int mt  = qq / JTILES;
            const int jt  = qq % JTILES;
            const int row0 = mt * TM;
            const int j0   = jt * TN;
            const float* __restrict__ Wm = isG ? Wg : Wt;

            unsigned long long acc[8][4];
            #pragma unroll
            for (int i = 0; i < 8; i++)
                #pragma unroll
                for (int j = 0; j < 4; j++) acc[i][j] = 0ull;

            for (int kt = 0; kt < KTILES; kt++) {
                const int kb4 = kt * (TK / 4);
                __syncthreads();
                #pragma unroll
                for (int it = 0; it < 4; it++) {
                    const int f  = it * NTHREADS + tid;
                    const int r  = f >> 3;
                    const int qd = f & 7;
                    int rr = row0 + r; if (rr >= B) rr = B - 1;
                    const float* arow;
                    if (isG) {
                        long long u = load_idx(uidx, rr, is64);
                        arow = user + (size_t)u * CDIM;
                    } else {
                        arow = text + (size_t)rr * SC;
                    }
                    const float4 va = __ldg(&((const float4*)arow)[kb4 + qd]);
                    const float4 vb = __ldg(&((const float4*)(Wm + (size_t)(j0 + r) * CDIM))[kb4 + qd]);
                    const int k0 = qd * 4;
                    As[k0 + 0][r] = va.x; As[k0 + 1][r] = va.y;
                    As[k0 + 2][r] = va.z; As[k0 + 3][r] = va.w;
                    Bs[k0 + 0][r] = vb.x; Bs[k0 + 1][r] = vb.y;
                    Bs[k0 + 2][r] = vb.z; Bs[k0 + 3][r] = vb.w;
                }
                __syncthreads();

                #pragma unroll 8
                for (int k = 0; k < TK; k++) {
                    const float4 a0 = *(const float4*)&As[k][ty * 8];
                    const float4 a1 = *(const float4*)&As[k][ty * 8 + 4];
                    const float4 b0 = *(const float4*)&Bs[k][tx * 8];
                    const float4 b1 = *(const float4*)&Bs[k][tx * 8 + 4];
                    unsigned long long bp[4];
                    {
                        float2 t0 = make_float2(b0.x, b0.y), t1 = make_float2(b0.z, b0.w);
                        float2 t2 = make_float2(b1.x, b1.y), t3 = make_float2(b1.z, b1.w);
                        bp[0] = *(unsigned long long*)&t0; bp[1] = *(unsigned long long*)&t1;
                        bp[2] = *(unsigned long long*)&t2; bp[3] = *(unsigned long long*)&t3;
                    }
                    const float av[8] = {a0.x, a0.y, a0.z, a0.w, a1.x, a1.y, a1.z, a1.w};
                    #pragma unroll
                    for (int ii = 0; ii < 8; ii++) {
                        const unsigned long long ad = dup2(av[ii]);
                        #pragma unroll
                        for (int jp = 0; jp < 4; jp++) fma2(acc[ii][jp], ad, bp[jp]);
                    }
                }
            }

            // epilogue: s_r += sum_j P[r,j]*x[r,j]; reduce over tx; atomicAdd
            #pragma unroll
            for (int ii = 0; ii < 8; ii++) {
                const int r = row0 + ty * 8 + ii;
                const int rr = (r < B) ? r : (B - 1);
                const float* xrow;
                if (isG) {
                    long long u = load_idx(uidx, rr, is64);
                    xrow = user + (size_t)u * CDIM;
                } else {
                    xrow = text + (size_t)rr * SC;
                }
                const float4 xa = __ldg(&((const float4*)xrow)[(j0 >> 2) + tx * 2]);
                const float4 xb = __ldg(&((const float4*)xrow)[(j0 >> 2) + tx * 2 + 1]);
                const float2 p0 = unpack2(acc[ii][0]);
                const float2 p1 = unpack2(acc[ii][1]);
                const float2 p2 = unpack2(acc[ii][2]);
                const float2 p3 = unpack2(acc[ii][3]);
                float s = p0.x * xa.x + p0.y * xa.y + p1.x * xa.z + p1.y * xa.w
                        + p2.x * xb.x + p2.y * xb.y + p3.x * xb.z + p3.y * xb.w;
                #pragma unroll
                for (int o = 8; o; o >>= 1) s += __shfl_xor_sync(0xffffffffu, s, o);
                if (tx == 0 && r < B) atomicAdd(&g_quad[isG * QOFF + r], s);
            }

            __syncthreads();
            if (tid == 0) s_item = atomicAdd(&g_ctr, 1u);
            __syncthreads();
            item = s_item;
        }
        else if (item < NITEMS) {
            // ============ streaming text copy chunk (unguarded) ============
            unsigned nG = g + 1; if (nG > NG) nG = NG;
            const unsigned chunk = item - nG;

            __syncthreads();
            if (tid == 0) s_item = atomicAdd(&g_ctr, 1u);   // prefetch next

            const size_t base = (size_t)chunk * CHUNK4 + tid;
            float4 v[8];
            #pragma unroll
            for (int j = 0; j < 8; j++)
                v[j] = __ldcs(&tin[base + (size_t)j * NTHREADS]);
            #pragma unroll
            for (int j = 0; j < 8; j++)
                __stcs(&dall[base + (size_t)j * NTHREADS], v[j]);

            __syncthreads();
            item = s_item;
        }
        else {
            // ================= finalize text rows =================
            const unsigned fitem = item - NITEMS;

            if (tid == 0) {
                while (*(volatile unsigned*)&g_passed < (unsigned)gridDim.x)
                    __nanosleep(100);
            }
            __syncthreads();
            __threadfence();

            const int r = (int)fitem * 8 + warp;
            if (r < B) {
                long long u = load_idx(uidx, r, is64);
                const float4* __restrict__ x4  = (const float4*)(text + (size_t)r * SC);
                const float4* __restrict__ g4  = (const float4*)(user + (size_t)u * CDIM);
                const float4* __restrict__ bt4 = (const float4*)bt;
                const float4* __restrict__ bg4 = (const float4*)bg;

                float4 xs[6], gs[6];
                float pxb = 0.f, pgb = 0.f, pxg = 0.f;
                #pragma unroll
                for (int k = 0; k < 6; k++) {
                    xs[k] = x4[lane + 32 * k];
                    gs[k] = g4[lane + 32 * k];
                    const float4 bv = bt4[lane + 32 * k];
                    const float4 gv = bg4[lane + 32 * k];
                    pxb += xs[k].x * bv.x + xs[k].y * bv.y + xs[k].z * bv.z + xs[k].w * bv.w;
                    pgb += gs[k].x * gv.x + gs[k].y * gv.y + gs[k].z * gv.z + gs[k].w * gv.w;
                    pxg += xs[k].x * gs[k].x + xs[k].y * gs[k].y + xs[k].z * gs[k].z + xs[k].w * gs[k].w;
                }
                #pragma unroll
                for (int o = 16; o; o >>= 1) {
                    pxb += __shfl_xor_sync(0xffffffffu, pxb, o);
                    pgb += __shfl_xor_sync(0xffffffffu, pgb, o);
                    pxg += __shfl_xor_sync(0xffffffffu, pxg, o);
                }
                float wa, wc;
                if (lane == 0) {
                    const float a  = g_quad[r] + pxb;          // text_ini . text_tmp
                    const float cq = g_quad[QOFF + r] + pgb;   // graph_tmp . graph_ini
                    const float bq = pxg;                      // graph_ini . text_ini
                    wa = 1.f / (1.f + expf(bq - a));
                    wc = 1.f / (1.f + expf(bq - cq));
                }
                wa = __shfl_sync(0xffffffffu, wa, 0);
                wc = __shfl_sync(0xffffffffu, wc, 0);
                const float wb = 1.f - wa, wd = 1.f - wc;

                float4* __restrict__ oT = (float4*)(outAll + (size_t)r * SC);
                float4* __restrict__ oU = (float4*)(g_ubuf + (size_t)r * CDIM);
                #pragma unroll
                for (int k = 0; k < 6; k++) {
                    float4 to, uo;
                    to.x = wa * xs[k].x + wb * gs[k].x;  uo.x = wc * gs[k].x + wd * xs[k].x;
                    to.y = wa * xs[k].y + wb * gs[k].y;  uo.y = wc * gs[k].y + wd * xs[k].y;
                    to.z = wa * xs[k].z + wb * gs[k].z;  uo.z = wc * gs[k].z + wd * xs[k].z;
                    to.w = wa * xs[k].w + wb * gs[k].w;  uo.w = wc * gs[k].w + wd * xs[k].w;
                    oT[lane + 32 * k] = to;
                    oU[lane + 32 * k] = uo;
                }
            }

            __syncthreads();
            if (tid == 0) s_item = atomicAdd(&g_ctr, 1u);
            __syncthreads();
            item = s_item;
        }
    }

    // ================= exit: last block resets state for next replay ======
    __syncthreads();
    if (tid == 0) {
        const unsigned t = atomicAdd(&g_exit, 1u);
        s_item = (t == gridDim.x - 1) ? 1u : 0u;
    }
    __syncthreads();
    if (s_item) {
        for (int i = tid; i < 2 * QOFF; i += NTHREADS) g_quad[i] = 0.f;
        __syncthreads();
        if (tid == 0) {
            __threadfence();
            g_ctr = 0u; g_passed = 0u;
            __threadfence();
            g_exit = 0u;
        }
    }
}

// ---------------------------------------------------------------------------
// Fixup: scatter precomputed blended user rows (g_ubuf) into outU.
// 8 rows per block (one per warp), L2-hot reads, ~4us.
// ---------------------------------------------------------------------------
__global__ void __launch_bounds__(NTHREADS)
fixup(const void* __restrict__ uidx,
      float* __restrict__ outAll,
      int B, long long text_n, long long user_rows)
{
    const int warp = threadIdx.x >> 5;
    const int lane = threadIdx.x & 31;
    const int r = blockIdx.x * 8 + warp;
    if (r >= B) return;
    const int is64 = detect_is64(uidx, B, user_rows);
    const long long u = load_idx(uidx, r, is64);

    const float4* __restrict__ src = (const float4*)(g_ubuf + (size_t)r * CDIM);
    float4* __restrict__ dst = (float4*)(outAll + text_n + (size_t)u * CDIM);
    #pragma unroll
    for (int k = 0; k < 6; k++)
        dst[lane + 32 * k] = src[lane + 32 * k];
}

// ---------------------------------------------------------------------------
extern "C" void kernel_launch(void* const* d_in, const int* in_sizes, int n_in,
                              void* d_out, int out_size)
{
    static cudaStream_t s2 = 0, s3 = 0;
    static cudaEvent_t evA = 0, evB = 0, evC = 0;
    static bool inited = false;
    if (!inited) {
        cudaStreamCreateWithFlags(&s2, cudaStreamNonBlocking);
        cudaStreamCreateWithFlags(&s3, cudaStreamNonBlocking);
        cudaEventCreateWithFlags(&evA, cudaEventDisableTiming);
        cudaEventCreateWithFlags(&evB, cudaEventDisableTiming);
        cudaEventCreateWithFlags(&evC, cudaEventDisableTiming);
        inited = true;
    }

    const float* text = (const float*)d_in[0];
    const float* user = (const float*)d_in[1];
    const void*  uidx = d_in[2];
    const float* Wt   = (const float*)d_in[3];
    const float* bt   = (const float*)d_in[4];
    const float* Wg   = (const float*)d_in[5];
    const float* bg   = (const float*)d_in[6];

    const long long text_n = in_sizes[0];
    const long long user_n = in_sizes[1];
    const int B = in_sizes[2];
    const long long SC = text_n / (long long)B;   // S*C
    const long long user_rows = user_n / CDIM;

    float* outAll = (float*)d_out;

    const unsigned perM = (unsigned)((B / TM) * JTILES);   // 96
    const unsigned NG = 2 * perM;                           // 192
    const size_t t4 = (size_t)text_n >> 2;
    const unsigned NCHUNK = (unsigned)((t4 + CHUNK4 - 1) / CHUNK4);
    const unsigned NITEMS = NG + NCHUNK;
    unsigned P = (NITEMS / 2) / NG;                         // spread over 1st half
    if (P < 1) P = 1;
    const unsigned NFIN = (unsigned)((B + 7) / 8);
    const unsigned TOTAL = NITEMS + NFIN;

    // fork: copy engines handle user -> outU, split across two streams so two
    // DMA engines can run in parallel (falls back gracefully if they share one)
    const size_t half_elems = ((size_t)user_n / 2) & ~((size_t)3);
    cudaEventRecord(evA, 0);
    cudaStreamWaitEvent(s2, evA, 0);
    cudaStreamWaitEvent(s3, evA, 0);
    cudaMemcpyAsync(outAll + text_n, user, half_elems * sizeof(float),
                    cudaMemcpyDeviceToDevice, s2);
    cudaMemcpyAsync(outAll + text_n + half_elems, user + half_elems,
                    ((size_t)user_n - half_elems) * sizeof(float),
                    cudaMemcpyDeviceToDevice, s3);
    cudaEventRecord(evB, s2);
    cudaEventRecord(evC, s3);

    mega<<<NBLOCKS, NTHREADS>>>(text, user, uidx, Wt, bt, Wg, bg,
                                outAll, B, SC, text_n, user_rows,
                                NG, P, NITEMS, TOTAL);

    // join, then overwrite the B indexed user rows from g_ubuf
    cudaStreamWaitEvent(0, evB, 0);
    cudaStreamWaitEvent(0, evC, 0);
    fixup<<<(B + 7) / 8, NTHREADS>>>(uidx, outAll, B, text_n, user_rows);
}

// round 8
// speedup vs baseline: 1.0005x; 1.0005x over previous
#include <cuda_runtime.h>

#define CDIM  768
#define CDIM4 192           // CDIM/4
#define NTHREADS 256
#define NBLOCKS  304        // 152 SMs * 2 blocks
#define TM 128
#define TN 128
#define TK 32
#define KTILES (CDIM / TK)  // 24
#define JTILES (CDIM / TN)  // 6
#define QOFF 4096           // scratch stride (max B = 4096)
#define CHUNK4 2048         // float4 per copy chunk (32 KB)
#define TMP (TM + 4)        // padded smem row

// quadratic-form scratch: [0,B) text, [QOFF,QOFF+B) graph. MUST be zero at
// kernel entry: zero-initialized at load; re-zeroed by last-exiting block.
__device__ float g_quad[2 * QOFF];
__device__ float g_ubuf[QOFF * CDIM];   // blended user rows (fallback path)
__device__ unsigned g_ctr;              // work-queue head
__device__ unsigned g_passed;           // blocks past all pre-finalize work
__device__ unsigned g_exit;             // exited blocks
__device__ unsigned g_valid = 1u;       // 1 iff user_index == arange(B)

// user_index may be int64 (declared) or int32 (JAX x64-off default).
__device__ __forceinline__ int detect_is64(const void* uptr, int B, long long nrows) {
    if (B < 2) return 1;
    long long v = ((const long long*)uptr)[B / 2 - 1];
    return (v >= 0 && v < nrows) ? 1 : 0;
}
__device__ __forceinline__ long long load_idx(const void* uptr, int i, int is64) {
    if (is64) return ((const long long*)uptr)[i];
    return (long long)((const int*)uptr)[i];
}

// ---- packed fp32x2 helpers (SASS FFMA2; ptxas never auto-fuses) ----
__device__ __forceinline__ unsigned long long dup2(float a) {
    unsigned long long d; unsigned ai = __float_as_uint(a);
    asm("mov.b64 %0, {%1, %1};" : "=l"(d) : "r"(ai));
    return d;
}
__device__ __forceinline__ void fma2(unsigned long long& acc,
                                     unsigned long long a, unsigned long long b) {
    asm("fma.rn.f32x2 %0, %1, %2, %0;" : "+l"(acc) : "l"(a), "l"(b));
}
__device__ __forceinline__ float2 unpack2(unsigned long long v) {
    float2 r;
    asm("mov.b64 {%0, %1}, %2;" : "=f"(r.x), "=f"(r.y) : "l"(v));
    return r;
}

// ---------------------------------------------------------------------------
// Mega kernel. Work items:
//   item 0:                      validate user_index == arange -> g_valid
//   items [1, NITEMS): mixed — t=(item-1); t%P==0 && t/P<NG -> GEMM tile;
//                      else copy chunk over [text | user rows [0,B)).
//   [NITEMS, TOTAL): finalize rows. Waits g_passed == gridDim.x, so all
//   copies + GEMM + validation are globally visible. If g_valid: blended
//   user rows go DIRECTLY to outU (CE never touches rows < B); else to
//   g_ubuf for the fixup scatter.
// ---------------------------------------------------------------------------
__global__ void __launch_bounds__(NTHREADS, 2)
mega(const float* __restrict__ text,
     const float* __restrict__ user,
     const void*  __restrict__ uidx,
     const float* __restrict__ Wt,
     const float* __restrict__ bt,
     const float* __restrict__ Wg,
     const float* __restrict__ bg,
     float* __restrict__ outAll,           // outT (text_n) then outU (user_n)
     int B, long long SC,
     long long text_n, long long user_rows,
     unsigned NG, unsigned P, unsigned NITEMS, unsigned TOTAL,
     unsigned NCHUNK_T, long long uh4ll)
{
    __shared__ float As[TK][TMP];
    __shared__ float Bs[TK][TMP];
    __shared__ unsigned s_item;

    const int tid  = threadIdx.x;
    const int warp = tid >> 5;
    const int lane = tid & 31;
    const int tx   = tid & 15;    // j-fragment index
    const int ty   = tid >> 4;    // row-fragment index

    const size_t t4  = (size_t)text_n >> 2;
    const size_t uh4 = (size_t)uh4ll;           // user-head float4 count
    const float4* __restrict__ tin = (const float4*)text;
    const float4* __restrict__ uin = (const float4*)user;
    float4* __restrict__ dall = (float4*)outAll;

    const unsigned perM = NG >> 1;

    if (tid == 0) s_item = atomicAdd(&g_ctr, 1u);
    __syncthreads();
    unsigned item = s_item;
    bool passed = false;

    const int is64 = detect_is64(uidx, B, user_rows);

    for (;;) {
        // once per block: signal that all its pre-finalize stores are visible
        if (!passed && item >= NITEMS) {
            __threadfence();
            __syncthreads();
            if (tid == 0) atomicAdd(&g_passed, 1u);
            passed = true;
        }
        if (item >= TOTAL) break;

        if (item == 0u) {
            // ================= validation item =================
            unsigned ok = 1u;
            for (int i = tid; i < B; i += NTHREADS)
                if (load_idx(uidx, i, is64) != (long long)i) ok = 0u;
            if (__ballot_sync(0xffffffffu, ok == 0u) && lane == 0)
                atomicAnd(&g_valid, 0u);
            __syncthreads();
            if (tid == 0) s_item = atomicAdd(&g_ctr, 1u);
            __syncthreads();
            item = s_item;
            continue;
        }

        const unsigned t = item - 1u;
        const unsigned g = t / P;
        const bool isGemm = (item < NITEMS) && (t - g * P == 0u) && (g < NG);

        if (isGemm) {
            // ================= GEMM bilinear-form tile =================
            const int isG = (g >= perM) ? 1 : 0;
            const int qq  = isG ? (int)(g - perM) : (int)g;
            const int mt  = qq / JTILES;
            const int jt  = qq % JTILES;
            const int row0 = mt * TM;
            const int j0   = jt * TN;
            const float* __restrict__ Wm = isG ? Wg : Wt;

            unsigned long long acc[8][4];
            #pragma unroll
            for (int i = 0; i < 8; i++)
                #pragma unroll
                for (int j = 0; j < 4; j++) acc[i][j] = 0ull;

            for (int kt = 0; kt < KTILES; kt++) {
                const int kb4 = kt * (TK / 4);
                __syncthreads();
                #pragma unroll
                for (int it = 0; it < 4; it++) {
                    const int f  = it * NTHREADS + tid;
                    const int r  = f >> 3;
                    const int qd = f & 7;
                    int rr = row0 + r; if (rr >= B) rr = B - 1;
                    const float* arow;
                    if (isG) {
                        long long u = load_idx(uidx, rr, is64);
                        arow = user + (size_t)u * CDIM;
                    } else {
                        arow = text + (size_t)rr * SC;
                    }
                    const float4 va = __ldg(&((const float4*)arow)[kb4 + qd]);
                    const float4 vb = __ldg(&((const float4*)(Wm + (size_t)(j0 + r) * CDIM))[kb4 + qd]);
                    const int k0 = qd * 4;
                    As[k0 + 0][r] = va.x; As[k0 + 1][r] = va.y;
                    As[k0 + 2][r] = va.z; As[k0 + 3][r] = va.w;
                    Bs[k0 + 0][r] = vb.x; Bs[k0 + 1][r] = vb.y;
                    Bs[k0 + 2][r] = vb.z; Bs[k0 + 3][r] = vb.w;
                }
                __syncthreads();

                #pragma unroll 8
                for (int k = 0; k < TK; k++) {
                    const float4 a0 = *(const float4*)&As[k][ty * 8];
                    const float4 a1 = *(const float4*)&As[k][ty * 8 + 4];
                    const float4 b0 = *(const float4*)&Bs[k][tx * 8];
                    const float4 b1 = *(const float4*)&Bs[k][tx * 8 + 4];
                    unsigned long long bp[4];
                    {
                        float2 t0 = make_float2(b0.x, b0.y), t1 = make_float2(b0.z, b0.w);
                        float2 t2 = make_float2(b1.x, b1.y), t3 = make_float2(b1.z, b1.w);
                        bp[0] = *(unsigned long long*)&t0; bp[1] = *(unsigned long long*)&t1;
                        bp[2] = *(unsigned long long*)&t2; bp[3] = *(unsigned long long*)&t3;
                    }
                    const float av[8] = {a0.x, a0.y, a0.z, a0.w, a1.x, a1.y, a1.z, a1.w};
                    #pragma unroll
                    for (int ii = 0; ii < 8; ii++) {
                        const unsigned long long ad = dup2(av[ii]);
                        #pragma unroll
                        for (int jp = 0; jp < 4; jp++) fma2(acc[ii][jp], ad, bp[jp]);
                    }
                }
            }

            // epilogue: s_r += sum_j P[r,j]*x[r,j]; reduce over tx; atomicAdd
            #pragma unroll
            for (int ii = 0; ii < 8; ii++) {
                const int r = row0 + ty * 8 + ii;
                const int rr = (r < B) ? r : (B - 1);
                const float* xrow;
                if (isG) {
                    long long u = load_idx(uidx, rr, is64);
                    xrow = user + (size_t)u * CDIM;
                } else {
                    xrow = text + (size_t)rr * SC;
                }
                const float4 xa = __ldg(&((const float4*)xrow)[(j0 >> 2) + tx * 2]);
                const float4 xb = __ldg(&((const float4*)xrow)[(j0 >> 2) + tx * 2 + 1]);
                const float2 p0 = unpack2(acc[ii][0]);
                const float2 p1 = unpack2(acc[ii][1]);
                const float2 p2 = unpack2(acc[ii][2]);
                const float2 p3 = unpack2(acc[ii][3]);
                float s = p0.x * xa.x + p0.y * xa.y + p1.x * xa.z + p1.y * xa.w
                        + p2.x * xb.x + p2.y * xb.y + p3.x * xb.z + p3.y * xb.w;
                #pragma unroll
                for (int o = 8; o; o >>= 1) s += __shfl_xor_sync(0xffffffffu, s, o);
                if (tx == 0 && r < B) atomicAdd(&g_quad[isG * QOFF + r], s);
            }

            __syncthreads();
            if (tid == 0) s_item = atomicAdd(&g_ctr, 1u);
            __syncthreads();
            item = s_item;
        }
        else if (item < NITEMS) {
            // ============ streaming copy chunk ============
            unsigned nG = g + 1; if (nG > NG) nG = NG;
            const unsigned chunk = t - nG;

            __syncthreads();
            if (tid == 0) s_item = atomicAdd(&g_ctr, 1u);   // prefetch next

            if (chunk < NCHUNK_T) {
                // text chunk
                const size_t base = (size_t)chunk * CHUNK4 + tid;
                if ((size_t)(chunk + 1) * CHUNK4 <= t4) {
                    float4 v[8];
                    #pragma unroll
                    for (int j = 0; j < 8; j++)
                        v[j] = __ldcs(&tin[base + (size_t)j * NTHREADS]);
                    #pragma unroll
                    for (int j = 0; j < 8; j++)
                        __stcs(&dall[base + (size_t)j * NTHREADS], v[j]);
                } else {
                    for (size_t i = base; i < t4; i += NTHREADS)
                        __stcs(&dall[i], __ldcs(&tin[i]));
                }
            } else {
                // user-head chunk: user rows [0,B) -> outU same offsets
                const unsigned cu = chunk - NCHUNK_T;
                const size_t base = (size_t)cu * CHUNK4 + tid;
                if ((size_t)(cu + 1) * CHUNK4 <= uh4) {
                    float4 v[8];
                    #pragma unroll
                    for (int j = 0; j < 8; j++)
                        v[j] = __ldcs(&uin[base + (size_t)j * NTHREADS]);
                    #pragma unroll
                    for (int j = 0; j < 8; j++)
                        __stcs(&dall[t4 + base + (size_t)j * NTHREADS], v[j]);
                } else {
                    for (size_t i = base; i < uh4; i += NTHREADS)
                        __stcs(&dall[t4 + i], __ldcs(&uin[i]));
                }
            }

            __syncthreads();
            item = s_item;
        }
        else {
            // ================= finalize rows =================
            const unsigned fitem = item - NITEMS;

            if (tid == 0) {
                while (*(volatile unsigned*)&g_passed < (unsigned)gridDim.x)
                    __nanosleep(100);
            }
            __syncthreads();
            __threadfence();
            const unsigned direct = *(volatile unsigned*)&g_valid;

            const int r = (int)fitem * 8 + warp;
            if (r < B) {
                long long u = load_idx(uidx, r, is64);
                const float4* __restrict__ x4  = (const float4*)(text + (size_t)r * SC);
                const float4* __restrict__ g4  = (const float4*)(user + (size_t)u * CDIM);
                const float4* __restrict__ bt4 = (const float4*)bt;
                const float4* __restrict__ bg4 = (const float4*)bg;

                float4 xs[6], gs[6];
                float pxb = 0.f, pgb = 0.f, pxg = 0.f;
                #pragma unroll
                for (int k = 0; k < 6; k++) {
                    xs[k] = x4[lane + 32 * k];
                    gs[k] = g4[lane + 32 * k];
                    const float4 bv = bt4[lane + 32 * k];
                    const float4 gv = bg4[lane + 32 * k];
                    pxb += xs[k].x * bv.x + xs[k].y * bv.y + xs[k].z * bv.z + xs[k].w * bv.w;
                    pgb += gs[k].x * gv.x + gs[k].y * gv.y + gs[k].z * gv.z + gs[k].w * gv.w;
                    pxg += xs[k].x * gs[k].x + xs[k].y * gs[k].y + xs[k].z * gs[k].z + xs[k].w * gs[k].w;
                }
                #pragma unroll
                for (int o = 16; o; o >>= 1) {
                    pxb += __shfl_xor_sync(0xffffffffu, pxb, o);
                    pgb += __shfl_xor_sync(0xffffffffu, pgb, o);
                    pxg += __shfl_xor_sync(0xffffffffu, pxg, o);
                }
                float wa, wc;
                if (lane == 0) {
                    const float a  = g_quad[r] + pxb;          // text_ini . text_tmp
                    const float cq = g_quad[QOFF + r] + pgb;   // graph_tmp . graph_ini
                    const float bq = pxg;                      // graph_ini . text_ini
                    wa = 1.f / (1.f + expf(bq - a));
                    wc = 1.f / (1.f + expf(bq - cq));
                }
                wa = __shfl_sync(0xffffffffu, wa, 0);
                wc = __shfl_sync(0xffffffffu, wc, 0);
                const float wb = 1.f - wa, wd = 1.f - wc;

                float4* __restrict__ oT = (float4*)(outAll + (size_t)r * SC);
                float4* __restrict__ oU = direct
                    ? (float4*)(outAll + text_n + (size_t)u * CDIM)
                    : (float4*)(g_ubuf + (size_t)r * CDIM);
                #pragma unroll
                for (int k = 0; k < 6; k++) {
                    float4 to, uo;
                    to.x = wa * xs[k].x + wb * gs[k].x;  uo.x = wc * gs[k].x + wd * xs[k].x;
                    to.y = wa * xs[k].y + wb * gs[k].y;  uo.y = wc * gs[k].y + wd * xs[k].y;
                    to.z = wa * xs[k].z + wb * gs[k].z;  uo.z = wc * gs[k].z + wd * xs[k].z;
                    to.w = wa * xs[k].w + wb * gs[k].w;  uo.w = wc * gs[k].w + wd * xs[k].w;
                    oT[lane + 32 * k] = to;
                    oU[lane + 32 * k] = uo;
                }
            }

            __syncthreads();
            if (tid == 0) s_item = atomicAdd(&g_ctr, 1u);
            __syncthreads();
            item = s_item;
        }
    }

    // ================= exit: last block resets state for next replay ======
    __syncthreads();
    if (tid == 0) {
        const unsigned tt = atomicAdd(&g_exit, 1u);
        s_item = (tt == gridDim.x - 1) ? 1u : 0u;
    }
    __syncthreads();
    if (s_item) {
        for (int i = tid; i < 2 * QOFF; i += NTHREADS) g_quad[i] = 0.f;
        __syncthreads();
        if (tid == 0) {
            __threadfence();
            g_ctr = 0u; g_passed = 0u; g_valid = 1u;
            __threadfence();
            g_exit = 0u;
        }
    }
}

// ---------------------------------------------------------------------------
// Fixup (fallback only): scatter g_ubuf rows into outU. No-op when g_valid.
// ---------------------------------------------------------------------------
__global__ void __launch_bounds__(NTHREADS)
fixup(const void* __restrict__ uidx,
      float* __restrict__ outAll,
      int B, long long text_n, long long user_rows)
{
    if (*(volatile unsigned*)&g_valid) return;   // direct mode: already written
    const int warp = threadIdx.x >> 5;
    const int lane = threadIdx.x & 31;
    const int r = blockIdx.x * 8 + warp;
    if (r >= B) return;
    const int is64 = detect_is64(uidx, B, user_rows);
    const long long u = load_idx(uidx, r, is64);

    const float4* __restrict__ src = (const float4*)(g_ubuf + (size_t)r * CDIM);
    float4* __restrict__ dst = (float4*)(outAll + text_n + (size_t)u * CDIM);
    #pragma unroll
    for (int k = 0; k < 6; k++)
        dst[lane + 32 * k] = src[lane + 32 * k];
}

// ---------------------------------------------------------------------------
extern "C" void kernel_launch(void* const* d_in, const int* in_sizes, int n_in,
                              void* d_out, int out_size)
{
    static cudaStream_t s2 = 0, s3 = 0;
    static cudaEvent_t evA = 0, evB = 0, evC = 0;
    static bool inited = false;
    if (!inited) {
        cudaStreamCreateWithFlags(&s2, cudaStreamNonBlocking);
        cudaStreamCreateWithFlags(&s3, cudaStreamNonBlocking);
        cudaEventCreateWithFlags(&evA, cudaEventDisableTiming);
        cudaEventCreateWithFlags(&evB, cudaEventDisableTiming);
        cudaEventCreateWithFlags(&evC, cudaEventDisableTiming);
        inited = true;
    }

    const float* text = (const float*)d_in[0];
    const float* user = (const float*)d_in[1];
    const void*  uidx = d_in[2];
    const float* Wt   = (const float*)d_in[3];
    const float* bt   = (const float*)d_in[4];
    const float* Wg   = (const float*)d_in[5];
    const float* bg   = (const float*)d_in[6];

    const long long text_n = in_sizes[0];
    const long long user_n = in_sizes[1];
    const int B = in_sizes[2];
    const long long SC = text_n / (long long)B;   // S*C
    const long long user_rows = user_n / CDIM;

    float* outAll = (float*)d_out;

    const unsigned perM = (unsigned)((B / TM) * JTILES);   // 96
    const unsigned NG = 2 * perM;                           // 192
    const size_t t4  = (size_t)text_n >> 2;
    const size_t uh  = (size_t)B * CDIM;                    // user-head floats
    const size_t uh4 = uh >> 2;
    const unsigned NCHUNK_T = (unsigned)((t4 + CHUNK4 - 1) / CHUNK4);
    const unsigned NCHUNK_U = (unsigned)((uh4 + CHUNK4 - 1) / CHUNK4);
    const unsigned NCHUNK = NCHUNK_T + NCHUNK_U;
    const unsigned NITEMS = 1 + NG + NCHUNK;
    unsigned P = (NCHUNK / 2) / NG;                         // spread over 1st half
    if (P < 1) P = 1;
    const unsigned NFIN = (unsigned)((B + 7) / 8);
    const unsigned TOTAL = NITEMS + NFIN;

    // fork: copy engines handle user rows [B, user_rows) -> outU tail,
    // split across two streams (two DMA engines if available).
    const size_t tail_elems = (size_t)user_n - uh;
    const size_t half_elems = (tail_elems / 2) & ~((size_t)3);
    cudaEventRecord(evA, 0);
    cudaStreamWaitEvent(s2, evA, 0);
    cudaStreamWaitEvent(s3, evA, 0);
    cudaMemcpyAsync(outAll + text_n + uh, user + uh, half_elems * sizeof(float),
                    cudaMemcpyDeviceToDevice, s2);
    cudaMemcpyAsync(outAll + text_n + uh + half_elems, user + uh + half_elems,
                    (tail_elems - half_elems) * sizeof(float),
                    cudaMemcpyDeviceToDevice, s3);
    cudaEventRecord(evB, s2);
    cudaEventRecord(evC, s3);

    mega<<<NBLOCKS, NTHREADS>>>(text, user, uidx, Wt, bt, Wg, bg,
                                outAll, B, SC, text_n, user_rows,
                                NG, P, NITEMS, TOTAL,
                                NCHUNK_T, (long long)uh4);

    // join, then (fallback only) scatter g_ubuf rows
    cudaStreamWaitEvent(0, evB, 0);
    cudaStreamWaitEvent(0, evC, 0);
    fixup<<<(B + 7) / 8, NTHREADS>>>(uidx, outAll, B, text_n, user_rows);
}